// round 3
// baseline (speedup 1.0000x reference)
#include <cuda_runtime.h>
#include <math.h>

#define BLOCK 256

// ---- dims ----
// 168 -> 84 -> 42 -> 21 -> 12 -> 10 -> 5 -> 2 -> 1

// ---- smem layout (float offsets), each segment padded to 4-float alignment ----
#define OFF_W1 0        // 14112
#define OFF_B1 14112    // 84
#define OFF_W2 14196    // 3528
#define OFF_B2 17724    // 42   (ends 17766)
#define OFF_W3 17768    // 882  (ends 18650)
#define OFF_B3 18652    // 21   (ends 18673)
#define OFF_W4 18676    // 252
#define OFF_B4 18928    // 12
#define OFF_W5 18940    // 120
#define OFF_B5 19060    // 10   (ends 19070)
#define OFF_W6 19072    // 50   (ends 19122)
#define OFF_B6 19124    // 5    (ends 19129)
#define OFF_W7 19132    // 10
#define OFF_B7 19144    // 2
#define OFF_W8 19148    // 2
#define OFF_B8 19152    // 1
#define SMEM_FLOATS 19156
#define SMEM_BYTES (SMEM_FLOATS * 4)

__device__ __forceinline__ void copy_smem(float* dst, const float* __restrict__ src, int n) {
    for (int i = threadIdx.x; i < n; i += BLOCK) dst[i] = src[i];
}

// Fully-unrolled dense layer: in[] / out[] are register arrays, weights broadcast from smem.
template<int IN, int OUT>
__device__ __forceinline__ void dense_relu(const float* __restrict__ sW,
                                           const float* __restrict__ sb,
                                           const float (&in)[IN], float (&out)[OUT]) {
#pragma unroll
    for (int j = 0; j < OUT; ++j) {
        float a = sb[j];
#pragma unroll
        for (int k = 0; k < IN; ++k) a = fmaf(in[k], sW[j * IN + k], a);
        out[j] = fmaxf(a, 0.0f);
    }
}

__global__ void __launch_bounds__(BLOCK, 1) mlp_kernel(
    const float* __restrict__ x,
    const float* __restrict__ W1, const float* __restrict__ b1,
    const float* __restrict__ W2, const float* __restrict__ b2,
    const float* __restrict__ W3, const float* __restrict__ b3,
    const float* __restrict__ W4, const float* __restrict__ b4,
    const float* __restrict__ W5, const float* __restrict__ b5,
    const float* __restrict__ W6, const float* __restrict__ b6,
    const float* __restrict__ W7, const float* __restrict__ b7,
    const float* __restrict__ W8, const float* __restrict__ b8,
    float* __restrict__ out, int batch)
{
    extern __shared__ float s[];
    copy_smem(s + OFF_W1, W1, 14112);
    copy_smem(s + OFF_B1, b1, 84);
    copy_smem(s + OFF_W2, W2, 3528);
    copy_smem(s + OFF_B2, b2, 42);
    copy_smem(s + OFF_W3, W3, 882);
    copy_smem(s + OFF_B3, b3, 21);
    copy_smem(s + OFF_W4, W4, 252);
    copy_smem(s + OFF_B4, b4, 12);
    copy_smem(s + OFF_W5, W5, 120);
    copy_smem(s + OFF_B5, b5, 10);
    copy_smem(s + OFF_W6, W6, 50);
    copy_smem(s + OFF_B6, b6, 5);
    copy_smem(s + OFF_W7, W7, 10);
    copy_smem(s + OFF_B7, b7, 2);
    copy_smem(s + OFF_W8, W8, 2);
    copy_smem(s + OFF_B8, b8, 1);
    __syncthreads();

    int row = blockIdx.x * BLOCK + threadIdx.x;
    if (row >= batch) return;

    // ---- layer 1: 168 -> 84 (x streamed from gmem in float4 chunks) ----
    float a1[84];
    {
        const float* sb1 = s + OFF_B1;
#pragma unroll
        for (int j = 0; j < 84; ++j) a1[j] = sb1[j];

        const float4* xr = reinterpret_cast<const float4*>(x + (size_t)row * 168);
        const float* sW1 = s + OFF_W1;
        for (int c = 0; c < 42; ++c) {   // rolled: keeps I$ footprint sane
            float4 xv = __ldg(&xr[c]);
#pragma unroll
            for (int j = 0; j < 84; ++j) {
                float4 wv = *reinterpret_cast<const float4*>(&sW1[j * 168 + c * 4]);
                a1[j] = fmaf(xv.x, wv.x, a1[j]);
                a1[j] = fmaf(xv.y, wv.y, a1[j]);
                a1[j] = fmaf(xv.z, wv.z, a1[j]);
                a1[j] = fmaf(xv.w, wv.w, a1[j]);
            }
        }
#pragma unroll
        for (int j = 0; j < 84; ++j) a1[j] = fmaxf(a1[j], 0.0f);
    }

    // ---- layers 2..7 in registers ----
    float a2[42]; dense_relu<84, 42>(s + OFF_W2, s + OFF_B2, a1, a2);
    float a3[21]; dense_relu<42, 21>(s + OFF_W3, s + OFF_B3, a2, a3);
    float a4[12]; dense_relu<21, 12>(s + OFF_W4, s + OFF_B4, a3, a4);
    float a5[10]; dense_relu<12, 10>(s + OFF_W5, s + OFF_B5, a4, a5);
    float a6[5];  dense_relu<10, 5>(s + OFF_W6, s + OFF_B6, a5, a6);
    float a7[2];  dense_relu<5, 2>(s + OFF_W7, s + OFF_B7, a6, a7);

    // ---- layer 8: 2 -> 1 + sigmoid ----
    float z = s[OFF_B8];
    z = fmaf(a7[0], s[OFF_W8 + 0], z);
    z = fmaf(a7[1], s[OFF_W8 + 1], z);
    out[row] = 1.0f / (1.0f + expf(-z));
}

extern "C" void kernel_launch(void* const* d_in, const int* in_sizes, int n_in,
                              void* d_out, int out_size) {
    const float* x  = (const float*)d_in[0];
    const float* W1 = (const float*)d_in[1];
    const float* b1 = (const float*)d_in[2];
    const float* W2 = (const float*)d_in[3];
    const float* b2 = (const float*)d_in[4];
    const float* W3 = (const float*)d_in[5];
    const float* b3 = (const float*)d_in[6];
    const float* W4 = (const float*)d_in[7];
    const float* b4 = (const float*)d_in[8];
    const float* W5 = (const float*)d_in[9];
    const float* b5 = (const float*)d_in[10];
    const float* W6 = (const float*)d_in[11];
    const float* b6 = (const float*)d_in[12];
    const float* W7 = (const float*)d_in[13];
    const float* b7 = (const float*)d_in[14];
    const float* W8 = (const float*)d_in[15];
    const float* b8 = (const float*)d_in[16];
    float* out = (float*)d_out;

    int batch = in_sizes[0] / 168;

    cudaFuncSetAttribute(mlp_kernel, cudaFuncAttributeMaxDynamicSharedMemorySize, SMEM_BYTES);

    int grid = (batch + BLOCK - 1) / BLOCK;
    mlp_kernel<<<grid, BLOCK, SMEM_BYTES>>>(
        x, W1, b1, W2, b2, W3, b3, W4, b4, W5, b5, W6, b6, W7, b7, W8, b8,
        out, batch);
}